// round 7
// baseline (speedup 1.0000x reference)
#include <cuda_runtime.h>
#include <cuda_fp16.h>
#include <cstdint>

#define D 128
#define NMAX 100000
#define EMAX 3200000
#define FULL 0xffffffffu

// Scratch in device globals (no runtime allocation).
__device__ float  g_h0[NMAX * D];
__device__ __half g_h1h[NMAX * D];      // h1 in fp16 (agg gather payload)
__device__ float  g_aself[NMAX];
__device__ float  g_aneigh[NMAX];
__device__ int    g_deg[NMAX];
__device__ int    g_off[NMAX + 1];
__device__ int    g_cur[NMAX];
__device__ int2   g_epack[EMAX];        // {col, f32 bits of a_neigh[col]}
__device__ int    g_bsum[512];
__device__ int    g_boff[512];

// ---------------------------------------------------------------------------
// Tensor-core GEMM (tf32 mma.sync m16n8k8).
// Grid (ceil(N/128), 2): cb=0 -> h0 (fp32) + a_self; cb=1 -> h1 (fp16) + a_neigh.
// ---------------------------------------------------------------------------
#define TSTRIDE 132
#define TILE_WORDS (128 * TSTRIDE)
#define GEMM_SMEM ((2 * TILE_WORDS + 3 * 128) * 4)

__device__ __forceinline__ uint32_t f2tf32(float f)
{
    uint32_t u;
    asm("cvt.rna.tf32.f32 %0, %1;" : "=r"(u) : "f"(f));
    return u;
}

__device__ __forceinline__ void mma_tf32(float* c, const uint32_t* a,
                                         uint32_t b0, uint32_t b1)
{
    asm volatile(
        "mma.sync.aligned.m16n8k8.row.col.f32.tf32.tf32.f32 "
        "{%0,%1,%2,%3}, {%4,%5,%6,%7}, {%8,%9}, {%0,%1,%2,%3};"
        : "+f"(c[0]), "+f"(c[1]), "+f"(c[2]), "+f"(c[3])
        : "r"(a[0]), "r"(a[1]), "r"(a[2]), "r"(a[3]), "r"(b0), "r"(b1));
}

__global__ __launch_bounds__(256) void gemm_kernel(
    const float* __restrict__ x,
    const float* __restrict__ W0, const float* __restrict__ b0,
    const float* __restrict__ W1, const float* __restrict__ b1,
    const float* __restrict__ att, int N)
{
    extern __shared__ uint32_t sm[];
    uint32_t* xs = sm;
    uint32_t* ws = sm + TILE_WORDS;
    float* rowsum = (float*)(sm + 2 * TILE_WORDS);
    float* sbias  = rowsum + 128;
    float* satt   = sbias + 128;

    const int tid  = threadIdx.x;
    const int row0 = blockIdx.x * 128;
    const int cb   = blockIdx.y;
    const float* W  = cb ? W1 : W0;
    const float* bv = cb ? b1 : b0;

    if (tid < 128) {
        rowsum[tid] = 0.0f;
        sbias[tid]  = bv[tid];
        satt[tid]   = att[cb * 128 + tid];
        if (cb == 0 && row0 + tid < N) g_deg[row0 + tid] = 0;
    }

    for (int i = tid; i < 128 * 128; i += 256) {
        int r = i >> 7, c = i & 127;
        int gr = row0 + r;
        float xv = (gr < N) ? x[(size_t)gr * 128 + c] : 0.0f;
        xs[r * TSTRIDE + c] = f2tf32(xv);
        ws[r * TSTRIDE + c] = f2tf32(W[r * 128 + c]);
    }
    __syncthreads();

    const int lane = tid & 31, wid = tid >> 5;
    const int gid  = lane >> 2, tg = lane & 3;
    const int mrow = (wid >> 1) * 32;
    const int ncol = (wid & 1) * 64;

    float acc[2][8][4];
#pragma unroll
    for (int mt = 0; mt < 2; mt++)
#pragma unroll
        for (int nt = 0; nt < 8; nt++)
#pragma unroll
            for (int q = 0; q < 4; q++) acc[mt][nt][q] = 0.0f;

#pragma unroll 2
    for (int ks = 0; ks < 16; ks++) {
        const int k0 = ks * 8;
        uint32_t a[2][4];
#pragma unroll
        for (int mt = 0; mt < 2; mt++) {
            int r = mrow + mt * 16 + gid;
            a[mt][0] = xs[(r    ) * TSTRIDE + k0 + tg    ];
            a[mt][1] = xs[(r + 8) * TSTRIDE + k0 + tg    ];
            a[mt][2] = xs[(r    ) * TSTRIDE + k0 + tg + 4];
            a[mt][3] = xs[(r + 8) * TSTRIDE + k0 + tg + 4];
        }
#pragma unroll
        for (int nt = 0; nt < 8; nt++) {
            int n = ncol + nt * 8 + gid;
            uint32_t bq0 = ws[n * TSTRIDE + k0 + tg    ];
            uint32_t bq1 = ws[n * TSTRIDE + k0 + tg + 4];
#pragma unroll
            for (int mt = 0; mt < 2; mt++)
                mma_tf32(acc[mt][nt], a[mt], bq0, bq1);
        }
    }

    float pr[2][2] = {{0.f, 0.f}, {0.f, 0.f}};
#pragma unroll
    for (int mt = 0; mt < 2; mt++) {
        int rbase = row0 + mrow + mt * 16;
#pragma unroll
        for (int nt = 0; nt < 8; nt++) {
            int n = ncol + nt * 8 + 2 * tg;
            float bia0 = sbias[n], bia1 = sbias[n + 1];
            float at0  = satt[n],  at1  = satt[n + 1];
            float v00 = fmaxf(acc[mt][nt][0] + bia0, 0.0f);
            float v01 = fmaxf(acc[mt][nt][1] + bia1, 0.0f);
            float v10 = fmaxf(acc[mt][nt][2] + bia0, 0.0f);
            float v11 = fmaxf(acc[mt][nt][3] + bia1, 0.0f);
            int r0r = rbase + gid, r1r = rbase + gid + 8;
            if (cb == 0) {
                if (r0r < N) *(float2*)(g_h0 + (size_t)r0r * 128 + n) = make_float2(v00, v01);
                if (r1r < N) *(float2*)(g_h0 + (size_t)r1r * 128 + n) = make_float2(v10, v11);
            } else {
                if (r0r < N) *(__half2*)(g_h1h + (size_t)r0r * 128 + n) =
                    __floats2half2_rn(v00, v01);
                if (r1r < N) *(__half2*)(g_h1h + (size_t)r1r * 128 + n) =
                    __floats2half2_rn(v10, v11);
            }
            pr[mt][0] += v00 * at0 + v01 * at1;
            pr[mt][1] += v10 * at0 + v11 * at1;
        }
    }
#pragma unroll
    for (int mt = 0; mt < 2; mt++)
#pragma unroll
        for (int h = 0; h < 2; h++) {
            float p = pr[mt][h];
            p += __shfl_xor_sync(FULL, p, 1);
            p += __shfl_xor_sync(FULL, p, 2);
            pr[mt][h] = p;
        }
    if (tg == 0) {
        atomicAdd(&rowsum[mrow + gid     ], pr[0][0]);
        atomicAdd(&rowsum[mrow + gid + 8 ], pr[0][1]);
        atomicAdd(&rowsum[mrow + gid + 16], pr[1][0]);
        atomicAdd(&rowsum[mrow + gid + 24], pr[1][1]);
    }
    __syncthreads();
    if (tid < 128) {
        int gr = row0 + tid;
        if (gr < N) {
            float p = rowsum[tid];
            p = (p > 0.0f) ? p : 0.2f * p;
            if (cb) g_aneigh[gr] = p;
            else    g_aself[gr]  = p;
        }
    }
}

// ---------------------------------------------------------------------------
// CSR build: histogram -> 3-kernel scan -> cursor scatter (packs e-values)
// ---------------------------------------------------------------------------
__global__ __launch_bounds__(256) void hist_kernel(const int* __restrict__ row, int E)
{
    int i = blockIdx.x * 256 + threadIdx.x;
    if (i < E) atomicAdd(&g_deg[row[i]], 1);
}

__global__ __launch_bounds__(512) void scan1_kernel(int N)
{
    int t = threadIdx.x, b = blockIdx.x;
    int i = b * 512 + t;
    int lane = t & 31, w = t >> 5;
    int v = (i < N) ? g_deg[i] : 0;
#pragma unroll
    for (int o = 1; o < 32; o <<= 1) {
        int n = __shfl_up_sync(FULL, v, o);
        if (lane >= o) v += n;
    }
    __shared__ int ws[16];
    if (lane == 31) ws[w] = v;
    __syncthreads();
    if (w == 0) {
        int s = (lane < 16) ? ws[lane] : 0;
#pragma unroll
        for (int o = 1; o < 16; o <<= 1) {
            int n = __shfl_up_sync(FULL, s, o);
            if (lane >= o) s += n;
        }
        if (lane < 16) ws[lane] = s;
    }
    __syncthreads();
    if (w > 0) v += ws[w - 1];
    if (i < N) g_off[i + 1] = v;
    if (t == 511) g_bsum[b] = v;
}

__global__ __launch_bounds__(512) void scan2_kernel(int nb)
{
    int t = threadIdx.x;
    int lane = t & 31, w = t >> 5;
    int orig = (t < nb) ? g_bsum[t] : 0;
    int v = orig;
#pragma unroll
    for (int o = 1; o < 32; o <<= 1) {
        int n = __shfl_up_sync(FULL, v, o);
        if (lane >= o) v += n;
    }
    __shared__ int ws[16];
    if (lane == 31) ws[w] = v;
    __syncthreads();
    if (w == 0) {
        int s = (lane < 16) ? ws[lane] : 0;
#pragma unroll
        for (int o = 1; o < 16; o <<= 1) {
            int n = __shfl_up_sync(FULL, s, o);
            if (lane >= o) s += n;
        }
        if (lane < 16) ws[lane] = s;
    }
    __syncthreads();
    if (w > 0) v += ws[w - 1];
    if (t < nb) g_boff[t] = v - orig;
}

__global__ __launch_bounds__(512) void scan3_kernel(int N)
{
    int t = threadIdx.x, b = blockIdx.x;
    int i = b * 512 + t;
    if (i < N) {
        int val = g_off[i + 1] + g_boff[b];
        g_off[i + 1] = val;
        g_cur[i] = val - g_deg[i];
    }
    if (i == 0) g_off[0] = 0;
}

__global__ __launch_bounds__(256) void scatter_kernel(
    const int* __restrict__ row, const int* __restrict__ col, int E)
{
    int i = blockIdx.x * 256 + threadIdx.x;
    if (i < E) {
        int c = col[i];
        int pos = atomicAdd(&g_cur[row[i]], 1);
        g_epack[pos] = make_int2(c, __float_as_int(g_aneigh[c]));
    }
}

// ---------------------------------------------------------------------------
// Aggregate + fused epilogue: one warp per node, HALF-WARP per edge.
// Lane l (sl = l&15) owns cols sl*8..sl*8+7; half-warp hw = l>>4 processes
// edge 2t+hw each step (2 edges in flight per warp, x4 unroll = MLP 8).
//   agg = sum_{(r,c)} (a_self[r]+a_neigh[c]) * h1[c]
//   out[r] = norm(h0[r],s0,o0) + norm(agg,s1,o1)
// ---------------------------------------------------------------------------
__global__ __launch_bounds__(256) void agg_kernel(
    const float* __restrict__ scale0, const float* __restrict__ offset0,
    const float* __restrict__ scale1, const float* __restrict__ offset1,
    float* __restrict__ out, int N)
{
    int gw = (blockIdx.x * blockDim.x + threadIdx.x) >> 5;
    int lane = threadIdx.x & 31;
    if (gw >= N) return;

    const int hw = lane >> 4;       // 0/1: which edge of the pair
    const int sl = lane & 15;       // col chunk: cols sl*8..sl*8+7

    const int start = g_off[gw];
    const int end   = g_off[gw + 1];
    const float a_r = g_aself[gw];

    float acc[8];
#pragma unroll
    for (int k = 0; k < 8; k++) acc[k] = 0.0f;

    for (int base = start; base < end; base += 32) {
        const int cnt = min(32, end - base);
        // Coalesced chunk load: lane i holds edge base+i.
        int2 p = (lane < cnt) ? g_epack[base + lane] : make_int2(0, 0);
        int   c = p.x;
        float e = (lane < cnt) ? a_r + __int_as_float(p.y) : 0.0f;

        const int npairs = (cnt + 1) >> 1;
#pragma unroll 4
        for (int t = 0; t < npairs; t++) {
            const int j = 2 * t + hw;                    // j<=32; e[j]=0 if invalid
            const float ej = __shfl_sync(FULL, e, j & 31);
            const int   cj = __shfl_sync(FULL, c, j & 31);
            const uint4 hp = ((const uint4*)(g_h1h + (size_t)cj * 128))[sl];
            const float2 f0 = __half22float2(*(const __half2*)&hp.x);
            const float2 f1 = __half22float2(*(const __half2*)&hp.y);
            const float2 f2 = __half22float2(*(const __half2*)&hp.z);
            const float2 f3 = __half22float2(*(const __half2*)&hp.w);
            acc[0] = fmaf(ej, f0.x, acc[0]);
            acc[1] = fmaf(ej, f0.y, acc[1]);
            acc[2] = fmaf(ej, f1.x, acc[2]);
            acc[3] = fmaf(ej, f1.y, acc[3]);
            acc[4] = fmaf(ej, f2.x, acc[4]);
            acc[5] = fmaf(ej, f2.y, acc[5]);
            acc[6] = fmaf(ej, f3.x, acc[6]);
            acc[7] = fmaf(ej, f3.y, acc[7]);
        }
    }

    // Fold the two half-warp accumulators: lanes 0-15 end up with the totals.
#pragma unroll
    for (int k = 0; k < 8; k++)
        acc[k] += __shfl_down_sync(FULL, acc[k], 16);

    const bool lo16 = (lane < 16);
    const float* h0row = g_h0 + (size_t)gw * 128;

    float4 h0a = make_float4(0.f, 0.f, 0.f, 0.f);
    float4 h0b = make_float4(0.f, 0.f, 0.f, 0.f);
    if (lo16) {
        h0a = *(const float4*)(h0row + sl * 8);
        h0b = *(const float4*)(h0row + sl * 8 + 4);
    }

    float s0 = 0.f, q0 = 0.f, s1 = 0.f, q1 = 0.f;
    if (lo16) {
        s0 = h0a.x + h0a.y + h0a.z + h0a.w + h0b.x + h0b.y + h0b.z + h0b.w;
        q0 = h0a.x * h0a.x + h0a.y * h0a.y + h0a.z * h0a.z + h0a.w * h0a.w
           + h0b.x * h0b.x + h0b.y * h0b.y + h0b.z * h0b.z + h0b.w * h0b.w;
#pragma unroll
        for (int k = 0; k < 8; k++) { s1 += acc[k]; q1 += acc[k] * acc[k]; }
    }
#pragma unroll
    for (int o = 16; o > 0; o >>= 1) {
        s0 += __shfl_xor_sync(FULL, s0, o);
        q0 += __shfl_xor_sync(FULL, q0, o);
        s1 += __shfl_xor_sync(FULL, s1, o);
        q1 += __shfl_xor_sync(FULL, q1, o);
    }

    const float m0 = s0 * (1.0f / 128.0f);
    const float i0 = rsqrtf(q0 * (1.0f / 128.0f) - m0 * m0 + 1e-9f);
    const float m1 = s1 * (1.0f / 128.0f);
    const float i1 = rsqrtf(q1 * (1.0f / 128.0f) - m1 * m1 + 1e-9f);

    if (lo16) {
        const float4 sc0a = *(const float4*)(scale0  + sl * 8);
        const float4 sc0b = *(const float4*)(scale0  + sl * 8 + 4);
        const float4 of0a = *(const float4*)(offset0 + sl * 8);
        const float4 of0b = *(const float4*)(offset0 + sl * 8 + 4);
        const float4 sc1a = *(const float4*)(scale1  + sl * 8);
        const float4 sc1b = *(const float4*)(scale1  + sl * 8 + 4);
        const float4 of1a = *(const float4*)(offset1 + sl * 8);
        const float4 of1b = *(const float4*)(offset1 + sl * 8 + 4);

        float4 oa, ob;
        oa.x = (h0a.x - m0) * sc0a.x * i0 + of0a.x + (acc[0] - m1) * sc1a.x * i1 + of1a.x;
        oa.y = (h0a.y - m0) * sc0a.y * i0 + of0a.y + (acc[1] - m1) * sc1a.y * i1 + of1a.y;
        oa.z = (h0a.z - m0) * sc0a.z * i0 + of0a.z + (acc[2] - m1) * sc1a.z * i1 + of1a.z;
        oa.w = (h0a.w - m0) * sc0a.w * i0 + of0a.w + (acc[3] - m1) * sc1a.w * i1 + of1a.w;
        ob.x = (h0b.x - m0) * sc0b.x * i0 + of0b.x + (acc[4] - m1) * sc1b.x * i1 + of1b.x;
        ob.y = (h0b.y - m0) * sc0b.y * i0 + of0b.y + (acc[5] - m1) * sc1b.y * i1 + of1b.y;
        ob.z = (h0b.z - m0) * sc0b.z * i0 + of0b.z + (acc[6] - m1) * sc1b.z * i1 + of1b.z;
        ob.w = (h0b.w - m0) * sc0b.w * i0 + of0b.w + (acc[7] - m1) * sc1b.w * i1 + of1b.w;

        float* orow = out + (size_t)gw * 128;
        *(float4*)(orow + sl * 8)     = oa;
        *(float4*)(orow + sl * 8 + 4) = ob;
    }
}

// ---------------------------------------------------------------------------
extern "C" void kernel_launch(void* const* d_in, const int* in_sizes, int n_in,
                              void* d_out, int out_size)
{
    const float* x       = (const float*)d_in[0];
    const int*   row     = (const int*)  d_in[1];
    const int*   col     = (const int*)  d_in[2];
    const float* W0      = (const float*)d_in[3];
    const float* b0      = (const float*)d_in[4];
    const float* W1      = (const float*)d_in[5];
    const float* b1      = (const float*)d_in[6];
    const float* att     = (const float*)d_in[7];
    const float* scale0  = (const float*)d_in[8];
    const float* offset0 = (const float*)d_in[9];
    const float* scale1  = (const float*)d_in[10];
    const float* offset1 = (const float*)d_in[11];
    float* out = (float*)d_out;

    const int N = in_sizes[0] / D;
    const int E = in_sizes[1];
    const int nb = (N + 511) / 512;

    cudaFuncSetAttribute(gemm_kernel, cudaFuncAttributeMaxDynamicSharedMemorySize,
                         GEMM_SMEM);

    dim3 ggrid((N + 127) / 128, 2);
    gemm_kernel<<<ggrid, 256, GEMM_SMEM>>>(x, W0, b0, W1, b1, att, N);
    hist_kernel<<<(E + 255) / 256, 256>>>(row, E);
    scan1_kernel<<<nb, 512>>>(N);
    scan2_kernel<<<1, 512>>>(nb);
    scan3_kernel<<<nb, 512>>>(N);
    scatter_kernel<<<(E + 255) / 256, 256>>>(row, col, E);
    agg_kernel<<<(N * 32 + 255) / 256, 256>>>(scale0, offset0, scale1, offset1, out, N);
}

// round 8
// speedup vs baseline: 1.0048x; 1.0048x over previous
#include <cuda_runtime.h>
#include <cuda_fp16.h>
#include <cstdint>

#define D 128
#define NMAX 100000
#define EMAX 3200000
#define FULL 0xffffffffu

// Scratch in device globals (no runtime allocation).
__device__ float  g_h0[NMAX * D];
__device__ __half g_h1h[NMAX * D];      // h1 in fp16 (agg gather payload)
__device__ float  g_aself[NMAX];
__device__ float  g_aneigh[NMAX];
__device__ int    g_deg[NMAX];
__device__ int    g_off[NMAX + 1];
__device__ int    g_cur[NMAX];
__device__ int2   g_epack[EMAX];        // {col, f32 bits of a_neigh[col]}
__device__ int    g_bsum[512];
__device__ int    g_boff[512];

// ---------------------------------------------------------------------------
// Tensor-core GEMM (tf32 mma.sync m16n8k8).
// Grid (ceil(N/128), 2): cb=0 -> h0 (fp32) + a_self; cb=1 -> h1 (fp16) + a_neigh.
// ---------------------------------------------------------------------------
#define TSTRIDE 132
#define TILE_WORDS (128 * TSTRIDE)
#define GEMM_SMEM ((2 * TILE_WORDS + 3 * 128) * 4)

__device__ __forceinline__ uint32_t f2tf32(float f)
{
    uint32_t u;
    asm("cvt.rna.tf32.f32 %0, %1;" : "=r"(u) : "f"(f));
    return u;
}

__device__ __forceinline__ void mma_tf32(float* c, const uint32_t* a,
                                         uint32_t b0, uint32_t b1)
{
    asm volatile(
        "mma.sync.aligned.m16n8k8.row.col.f32.tf32.tf32.f32 "
        "{%0,%1,%2,%3}, {%4,%5,%6,%7}, {%8,%9}, {%0,%1,%2,%3};"
        : "+f"(c[0]), "+f"(c[1]), "+f"(c[2]), "+f"(c[3])
        : "r"(a[0]), "r"(a[1]), "r"(a[2]), "r"(a[3]), "r"(b0), "r"(b1));
}

__global__ __launch_bounds__(256) void gemm_kernel(
    const float* __restrict__ x,
    const float* __restrict__ W0, const float* __restrict__ b0,
    const float* __restrict__ W1, const float* __restrict__ b1,
    const float* __restrict__ att, int N)
{
    extern __shared__ uint32_t sm[];
    uint32_t* xs = sm;
    uint32_t* ws = sm + TILE_WORDS;
    float* rowsum = (float*)(sm + 2 * TILE_WORDS);
    float* sbias  = rowsum + 128;
    float* satt   = sbias + 128;

    const int tid  = threadIdx.x;
    const int row0 = blockIdx.x * 128;
    const int cb   = blockIdx.y;
    const float* W  = cb ? W1 : W0;
    const float* bv = cb ? b1 : b0;

    if (tid < 128) {
        rowsum[tid] = 0.0f;
        sbias[tid]  = bv[tid];
        satt[tid]   = att[cb * 128 + tid];
        if (cb == 0 && row0 + tid < N) g_deg[row0 + tid] = 0;
    }

    for (int i = tid; i < 128 * 128; i += 256) {
        int r = i >> 7, c = i & 127;
        int gr = row0 + r;
        float xv = (gr < N) ? x[(size_t)gr * 128 + c] : 0.0f;
        xs[r * TSTRIDE + c] = f2tf32(xv);
        ws[r * TSTRIDE + c] = f2tf32(W[r * 128 + c]);
    }
    __syncthreads();

    const int lane = tid & 31, wid = tid >> 5;
    const int gid  = lane >> 2, tg = lane & 3;
    const int mrow = (wid >> 1) * 32;
    const int ncol = (wid & 1) * 64;

    float acc[2][8][4];
#pragma unroll
    for (int mt = 0; mt < 2; mt++)
#pragma unroll
        for (int nt = 0; nt < 8; nt++)
#pragma unroll
            for (int q = 0; q < 4; q++) acc[mt][nt][q] = 0.0f;

#pragma unroll 2
    for (int ks = 0; ks < 16; ks++) {
        const int k0 = ks * 8;
        uint32_t a[2][4];
#pragma unroll
        for (int mt = 0; mt < 2; mt++) {
            int r = mrow + mt * 16 + gid;
            a[mt][0] = xs[(r    ) * TSTRIDE + k0 + tg    ];
            a[mt][1] = xs[(r + 8) * TSTRIDE + k0 + tg    ];
            a[mt][2] = xs[(r    ) * TSTRIDE + k0 + tg + 4];
            a[mt][3] = xs[(r + 8) * TSTRIDE + k0 + tg + 4];
        }
#pragma unroll
        for (int nt = 0; nt < 8; nt++) {
            int n = ncol + nt * 8 + gid;
            uint32_t bq0 = ws[n * TSTRIDE + k0 + tg    ];
            uint32_t bq1 = ws[n * TSTRIDE + k0 + tg + 4];
#pragma unroll
            for (int mt = 0; mt < 2; mt++)
                mma_tf32(acc[mt][nt], a[mt], bq0, bq1);
        }
    }

    float pr[2][2] = {{0.f, 0.f}, {0.f, 0.f}};
#pragma unroll
    for (int mt = 0; mt < 2; mt++) {
        int rbase = row0 + mrow + mt * 16;
#pragma unroll
        for (int nt = 0; nt < 8; nt++) {
            int n = ncol + nt * 8 + 2 * tg;
            float bia0 = sbias[n], bia1 = sbias[n + 1];
            float at0  = satt[n],  at1  = satt[n + 1];
            float v00 = fmaxf(acc[mt][nt][0] + bia0, 0.0f);
            float v01 = fmaxf(acc[mt][nt][1] + bia1, 0.0f);
            float v10 = fmaxf(acc[mt][nt][2] + bia0, 0.0f);
            float v11 = fmaxf(acc[mt][nt][3] + bia1, 0.0f);
            int r0r = rbase + gid, r1r = rbase + gid + 8;
            if (cb == 0) {
                if (r0r < N) *(float2*)(g_h0 + (size_t)r0r * 128 + n) = make_float2(v00, v01);
                if (r1r < N) *(float2*)(g_h0 + (size_t)r1r * 128 + n) = make_float2(v10, v11);
            } else {
                if (r0r < N) *(__half2*)(g_h1h + (size_t)r0r * 128 + n) =
                    __floats2half2_rn(v00, v01);
                if (r1r < N) *(__half2*)(g_h1h + (size_t)r1r * 128 + n) =
                    __floats2half2_rn(v10, v11);
            }
            pr[mt][0] += v00 * at0 + v01 * at1;
            pr[mt][1] += v10 * at0 + v11 * at1;
        }
    }
#pragma unroll
    for (int mt = 0; mt < 2; mt++)
#pragma unroll
        for (int h = 0; h < 2; h++) {
            float p = pr[mt][h];
            p += __shfl_xor_sync(FULL, p, 1);
            p += __shfl_xor_sync(FULL, p, 2);
            pr[mt][h] = p;
        }
    if (tg == 0) {
        atomicAdd(&rowsum[mrow + gid     ], pr[0][0]);
        atomicAdd(&rowsum[mrow + gid + 8 ], pr[0][1]);
        atomicAdd(&rowsum[mrow + gid + 16], pr[1][0]);
        atomicAdd(&rowsum[mrow + gid + 24], pr[1][1]);
    }
    __syncthreads();
    if (tid < 128) {
        int gr = row0 + tid;
        if (gr < N) {
            float p = rowsum[tid];
            p = (p > 0.0f) ? p : 0.2f * p;
            if (cb) g_aneigh[gr] = p;
            else    g_aself[gr]  = p;
        }
    }
}

// ---------------------------------------------------------------------------
// CSR build: histogram -> 3-kernel scan -> cursor scatter (packs e-values)
// ---------------------------------------------------------------------------
__global__ __launch_bounds__(256) void hist_kernel(const int* __restrict__ row, int E)
{
    int i = blockIdx.x * 256 + threadIdx.x;
    if (i < E) atomicAdd(&g_deg[row[i]], 1);
}

__global__ __launch_bounds__(512) void scan1_kernel(int N)
{
    int t = threadIdx.x, b = blockIdx.x;
    int i = b * 512 + t;
    int lane = t & 31, w = t >> 5;
    int v = (i < N) ? g_deg[i] : 0;
#pragma unroll
    for (int o = 1; o < 32; o <<= 1) {
        int n = __shfl_up_sync(FULL, v, o);
        if (lane >= o) v += n;
    }
    __shared__ int ws[16];
    if (lane == 31) ws[w] = v;
    __syncthreads();
    if (w == 0) {
        int s = (lane < 16) ? ws[lane] : 0;
#pragma unroll
        for (int o = 1; o < 16; o <<= 1) {
            int n = __shfl_up_sync(FULL, s, o);
            if (lane >= o) s += n;
        }
        if (lane < 16) ws[lane] = s;
    }
    __syncthreads();
    if (w > 0) v += ws[w - 1];
    if (i < N) g_off[i + 1] = v;
    if (t == 511) g_bsum[b] = v;
}

__global__ __launch_bounds__(512) void scan2_kernel(int nb)
{
    int t = threadIdx.x;
    int lane = t & 31, w = t >> 5;
    int orig = (t < nb) ? g_bsum[t] : 0;
    int v = orig;
#pragma unroll
    for (int o = 1; o < 32; o <<= 1) {
        int n = __shfl_up_sync(FULL, v, o);
        if (lane >= o) v += n;
    }
    __shared__ int ws[16];
    if (lane == 31) ws[w] = v;
    __syncthreads();
    if (w == 0) {
        int s = (lane < 16) ? ws[lane] : 0;
#pragma unroll
        for (int o = 1; o < 16; o <<= 1) {
            int n = __shfl_up_sync(FULL, s, o);
            if (lane >= o) s += n;
        }
        if (lane < 16) ws[lane] = s;
    }
    __syncthreads();
    if (w > 0) v += ws[w - 1];
    if (t < nb) g_boff[t] = v - orig;
}

__global__ __launch_bounds__(512) void scan3_kernel(int N)
{
    int t = threadIdx.x, b = blockIdx.x;
    int i = b * 512 + t;
    if (i < N) {
        int val = g_off[i + 1] + g_boff[b];
        g_off[i + 1] = val;
        g_cur[i] = val - g_deg[i];
    }
    if (i == 0) g_off[0] = 0;
}

__global__ __launch_bounds__(256) void scatter_kernel(
    const int* __restrict__ row, const int* __restrict__ col, int E)
{
    int i = blockIdx.x * 256 + threadIdx.x;
    if (i < E) {
        int c = col[i];
        int pos = atomicAdd(&g_cur[row[i]], 1);
        g_epack[pos] = make_int2(c, __float_as_int(g_aneigh[c]));
    }
}

// ---------------------------------------------------------------------------
// Aggregate + fused epilogue: one warp per node, HALF-WARP per edge.
// Lane l (sl = l&15) owns cols sl*8..sl*8+7; half-warp hw = l>>4 processes
// edge 2t+hw each step (2 edges in flight per warp, x4 unroll = MLP 8).
//   agg = sum_{(r,c)} (a_self[r]+a_neigh[c]) * h1[c]
//   out[r] = norm(h0[r],s0,o0) + norm(agg,s1,o1)
// ---------------------------------------------------------------------------
__global__ __launch_bounds__(256) void agg_kernel(
    const float* __restrict__ scale0, const float* __restrict__ offset0,
    const float* __restrict__ scale1, const float* __restrict__ offset1,
    float* __restrict__ out, int N)
{
    int gw = (blockIdx.x * blockDim.x + threadIdx.x) >> 5;
    int lane = threadIdx.x & 31;
    if (gw >= N) return;

    const int hw = lane >> 4;       // 0/1: which edge of the pair
    const int sl = lane & 15;       // col chunk: cols sl*8..sl*8+7

    const int start = g_off[gw];
    const int end   = g_off[gw + 1];
    const float a_r = g_aself[gw];

    float acc[8];
#pragma unroll
    for (int k = 0; k < 8; k++) acc[k] = 0.0f;

    for (int base = start; base < end; base += 32) {
        const int cnt = min(32, end - base);
        // Coalesced chunk load: lane i holds edge base+i.
        int2 p = (lane < cnt) ? g_epack[base + lane] : make_int2(0, 0);
        int   c = p.x;
        float e = (lane < cnt) ? a_r + __int_as_float(p.y) : 0.0f;

        const int npairs = (cnt + 1) >> 1;
#pragma unroll 4
        for (int t = 0; t < npairs; t++) {
            const int j = 2 * t + hw;                    // j<=32; e[j]=0 if invalid
            const float ej = __shfl_sync(FULL, e, j & 31);
            const int   cj = __shfl_sync(FULL, c, j & 31);
            const uint4 hp = ((const uint4*)(g_h1h + (size_t)cj * 128))[sl];
            const float2 f0 = __half22float2(*(const __half2*)&hp.x);
            const float2 f1 = __half22float2(*(const __half2*)&hp.y);
            const float2 f2 = __half22float2(*(const __half2*)&hp.z);
            const float2 f3 = __half22float2(*(const __half2*)&hp.w);
            acc[0] = fmaf(ej, f0.x, acc[0]);
            acc[1] = fmaf(ej, f0.y, acc[1]);
            acc[2] = fmaf(ej, f1.x, acc[2]);
            acc[3] = fmaf(ej, f1.y, acc[3]);
            acc[4] = fmaf(ej, f2.x, acc[4]);
            acc[5] = fmaf(ej, f2.y, acc[5]);
            acc[6] = fmaf(ej, f3.x, acc[6]);
            acc[7] = fmaf(ej, f3.y, acc[7]);
        }
    }

    // Fold the two half-warp accumulators: lanes 0-15 end up with the totals.
#pragma unroll
    for (int k = 0; k < 8; k++)
        acc[k] += __shfl_down_sync(FULL, acc[k], 16);

    const bool lo16 = (lane < 16);
    const float* h0row = g_h0 + (size_t)gw * 128;

    float4 h0a = make_float4(0.f, 0.f, 0.f, 0.f);
    float4 h0b = make_float4(0.f, 0.f, 0.f, 0.f);
    if (lo16) {
        h0a = *(const float4*)(h0row + sl * 8);
        h0b = *(const float4*)(h0row + sl * 8 + 4);
    }

    float s0 = 0.f, q0 = 0.f, s1 = 0.f, q1 = 0.f;
    if (lo16) {
        s0 = h0a.x + h0a.y + h0a.z + h0a.w + h0b.x + h0b.y + h0b.z + h0b.w;
        q0 = h0a.x * h0a.x + h0a.y * h0a.y + h0a.z * h0a.z + h0a.w * h0a.w
           + h0b.x * h0b.x + h0b.y * h0b.y + h0b.z * h0b.z + h0b.w * h0b.w;
#pragma unroll
        for (int k = 0; k < 8; k++) { s1 += acc[k]; q1 += acc[k] * acc[k]; }
    }
#pragma unroll
    for (int o = 16; o > 0; o >>= 1) {
        s0 += __shfl_xor_sync(FULL, s0, o);
        q0 += __shfl_xor_sync(FULL, q0, o);
        s1 += __shfl_xor_sync(FULL, s1, o);
        q1 += __shfl_xor_sync(FULL, q1, o);
    }

    const float m0 = s0 * (1.0f / 128.0f);
    const float i0 = rsqrtf(q0 * (1.0f / 128.0f) - m0 * m0 + 1e-9f);
    const float m1 = s1 * (1.0f / 128.0f);
    const float i1 = rsqrtf(q1 * (1.0f / 128.0f) - m1 * m1 + 1e-9f);

    if (lo16) {
        const float4 sc0a = *(const float4*)(scale0  + sl * 8);
        const float4 sc0b = *(const float4*)(scale0  + sl * 8 + 4);
        const float4 of0a = *(const float4*)(offset0 + sl * 8);
        const float4 of0b = *(const float4*)(offset0 + sl * 8 + 4);
        const float4 sc1a = *(const float4*)(scale1  + sl * 8);
        const float4 sc1b = *(const float4*)(scale1  + sl * 8 + 4);
        const float4 of1a = *(const float4*)(offset1 + sl * 8);
        const float4 of1b = *(const float4*)(offset1 + sl * 8 + 4);

        float4 oa, ob;
        oa.x = (h0a.x - m0) * sc0a.x * i0 + of0a.x + (acc[0] - m1) * sc1a.x * i1 + of1a.x;
        oa.y = (h0a.y - m0) * sc0a.y * i0 + of0a.y + (acc[1] - m1) * sc1a.y * i1 + of1a.y;
        oa.z = (h0a.z - m0) * sc0a.z * i0 + of0a.z + (acc[2] - m1) * sc1a.z * i1 + of1a.z;
        oa.w = (h0a.w - m0) * sc0a.w * i0 + of0a.w + (acc[3] - m1) * sc1a.w * i1 + of1a.w;
        ob.x = (h0b.x - m0) * sc0b.x * i0 + of0b.x + (acc[4] - m1) * sc1b.x * i1 + of1b.x;
        ob.y = (h0b.y - m0) * sc0b.y * i0 + of0b.y + (acc[5] - m1) * sc1b.y * i1 + of1b.y;
        ob.z = (h0b.z - m0) * sc0b.z * i0 + of0b.z + (acc[6] - m1) * sc1b.z * i1 + of1b.z;
        ob.w = (h0b.w - m0) * sc0b.w * i0 + of0b.w + (acc[7] - m1) * sc1b.w * i1 + of1b.w;

        float* orow = out + (size_t)gw * 128;
        *(float4*)(orow + sl * 8)     = oa;
        *(float4*)(orow + sl * 8 + 4) = ob;
    }
}

// ---------------------------------------------------------------------------
extern "C" void kernel_launch(void* const* d_in, const int* in_sizes, int n_in,
                              void* d_out, int out_size)
{
    const float* x       = (const float*)d_in[0];
    const int*   row     = (const int*)  d_in[1];
    const int*   col     = (const int*)  d_in[2];
    const float* W0      = (const float*)d_in[3];
    const float* b0      = (const float*)d_in[4];
    const float* W1      = (const float*)d_in[5];
    const float* b1      = (const float*)d_in[6];
    const float* att     = (const float*)d_in[7];
    const float* scale0  = (const float*)d_in[8];
    const float* offset0 = (const float*)d_in[9];
    const float* scale1  = (const float*)d_in[10];
    const float* offset1 = (const float*)d_in[11];
    float* out = (float*)d_out;

    const int N = in_sizes[0] / D;
    const int E = in_sizes[1];
    const int nb = (N + 511) / 512;

    cudaFuncSetAttribute(gemm_kernel, cudaFuncAttributeMaxDynamicSharedMemorySize,
                         GEMM_SMEM);

    dim3 ggrid((N + 127) / 128, 2);
    gemm_kernel<<<ggrid, 256, GEMM_SMEM>>>(x, W0, b0, W1, b1, att, N);
    hist_kernel<<<(E + 255) / 256, 256>>>(row, E);
    scan1_kernel<<<nb, 512>>>(N);
    scan2_kernel<<<1, 512>>>(nb);
    scan3_kernel<<<nb, 512>>>(N);
    scatter_kernel<<<(E + 255) / 256, 256>>>(row, col, E);
    agg_kernel<<<(N * 32 + 255) / 256, 256>>>(scale0, offset0, scale1, offset1, out, N);
}